// round 5
// baseline (speedup 1.0000x reference)
#include <cuda_runtime.h>
#include <cuda_bf16.h>
#include <math.h>

// Problem constants
#define B  2
#define N  512
#define FI 256
#define FO 128
#define ALPHA 0.2f

// e-kernel tiling
#define TJ 32
#define TI 32
#define NPART (B * (N/TI) * (N/TJ))   // 512

// fused kernel tiling
#define MT 8           // rows per CTA
#define KTF 16         // Wh smem sub-tile depth (per K-half)

typedef unsigned long long ull;

// Scratch (no allocations allowed -> device globals)
__device__ float g_Wh[B * N * FO];        // 512 KB
__device__ float g_e [B * N * N];         // 2 MB (masked e: -inf where adj==0)
__device__ float g_c [B * N];             // ci = sum_o a_o * Wh[i,o]
__device__ float g_part[NPART];

__device__ __forceinline__ ull fadd2(ull a, ull b) {
    ull d; asm("add.rn.f32x2 %0, %1, %2;" : "=l"(d) : "l"(a), "l"(b)); return d;
}
__device__ __forceinline__ ull ffma2(ull a, ull b, ull c) {
    ull d; asm("fma.rn.f32x2 %0, %1, %2, %3;" : "=l"(d) : "l"(a), "l"(b), "l"(c)); return d;
}
__device__ __forceinline__ float lo_f(ull v) { return __uint_as_float((unsigned)(v & 0xFFFFFFFFull)); }
__device__ __forceinline__ float hi_f(ull v) { return __uint_as_float((unsigned)(v >> 32)); }

#define ABS2_MASK 0x7FFFFFFF7FFFFFFFull

// ---------------------------------------------------------------------------
// Kernel A: Wh = x @ W  (+ ci = Wh . a_fc)
// grid: B*N/4, block: 128.  thread: row r = tx>>5 (4 rows/CTA), o4 = tx&31.
// ---------------------------------------------------------------------------
__global__ void k_gemm(const float* __restrict__ x, const float* __restrict__ W,
                       const float* __restrict__ a_fc) {
    const int row0 = blockIdx.x * 4;
    const int tx   = threadIdx.x;
    const int r    = tx >> 5;
    const int lane = tx & 31;

    __shared__ float xs[4][FI];
    {
        const float4* x4 = reinterpret_cast<const float4*>(x + row0 * FI);
        float4* xs4 = reinterpret_cast<float4*>(&xs[0][0]);
        xs4[tx]       = x4[tx];
        xs4[tx + 128] = x4[tx + 128];
    }
    __syncthreads();

    const float4* W4 = reinterpret_cast<const float4*>(W);   // [FI][FO/4]
    float4 acc = make_float4(0.f, 0.f, 0.f, 0.f);

    #pragma unroll 8
    for (int f = 0; f < FI; f++) {
        const float4 w = W4[f * (FO/4) + lane];
        const float xv = xs[r][f];
        acc.x = fmaf(xv, w.x, acc.x);
        acc.y = fmaf(xv, w.y, acc.y);
        acc.z = fmaf(xv, w.z, acc.z);
        acc.w = fmaf(xv, w.w, acc.w);
    }

    reinterpret_cast<float4*>(g_Wh)[(row0 + r) * (FO/4) + lane] = acc;

    // ci = sum_o a_o * Wh[row, o]
    const float4 av = reinterpret_cast<const float4*>(a_fc)[lane];
    float m = acc.x * av.x + acc.y * av.y + acc.z * av.z + acc.w * av.w;
    #pragma unroll
    for (int off = 16; off > 0; off >>= 1)
        m += __shfl_xor_sync(0xFFFFFFFFu, m, off);
    if (lane == 0) g_c[row0 + r] = m;
}

// ---------------------------------------------------------------------------
// Kernel B: e[b,i,j] = 0.6*(ci+cj) + 0.4 * sum_o a_o * |Wh_i,o + Wh_j,o|
//           stores (adj != 0 ? e : -inf); ss partial uses UNMASKED e
//           (reference computes the global norm before masking)
// grid: (N/TJ, N/TI, B), block: (32, 8) -> each thread 4 i's, 1 j
// ---------------------------------------------------------------------------
__global__ void k_edges(const float* __restrict__ a_fc, const int* __restrict__ adj) {
    const int b  = blockIdx.z;
    const int it = blockIdx.y * TI;
    const int jt = blockIdx.x * TJ;
    const int tx = threadIdx.x;
    const int ty = threadIdx.y;
    const int tid = ty * 32 + tx;

    __shared__ float4 tIs[TI * 33];
    __shared__ float4 tJs[TJ * 33];
    __shared__ float4 aS[FO / 4];
    __shared__ float  cIs[TI];
    __shared__ float  cJs[TJ];

    const float4* Wh4 = reinterpret_cast<const float4*>(g_Wh);
    const float4* a4  = reinterpret_cast<const float4*>(a_fc);

    if (tid < FO / 4) aS[tid] = a4[tid];
    if (tid >= 64 && tid < 96)  cIs[tid - 64] = 0.6f * g_c[b * N + it + (tid - 64)];
    if (tid >= 96 && tid < 128) cJs[tid - 96] = 0.6f * g_c[b * N + jt + (tid - 96)];

    #pragma unroll
    for (int p = 0; p < 4; p++) {
        int idx = tid + 256 * p;
        int r = idx >> 5, c = idx & 31;
        tIs[r * 33 + c] = Wh4[(b * N + it + r) * (FO / 4) + c];
        tJs[r * 33 + c] = Wh4[(b * N + jt + r) * (FO / 4) + c];
    }
    __syncthreads();

    const ulonglong2* tI2 = reinterpret_cast<const ulonglong2*>(tIs);
    const ulonglong2* tJ2 = reinterpret_cast<const ulonglong2*>(tJs);
    const ulonglong2* a2  = reinterpret_cast<const ulonglong2*>(aS);

    ull accA[4] = {0, 0, 0, 0};
    ull accB[4] = {0, 0, 0, 0};

    #pragma unroll 4
    for (int oc = 0; oc < FO / 4; oc++) {
        const ulonglong2 wj = tJ2[tx * 33 + oc];       // lane-varying
        const ulonglong2 av = a2[oc];                  // broadcast
        #pragma unroll
        for (int k = 0; k < 4; k++) {
            const ulonglong2 wi = tI2[(ty + 8 * k) * 33 + oc];  // warp broadcast
            ull s0 = fadd2(wi.x, wj.x) & ABS2_MASK;
            ull s1 = fadd2(wi.y, wj.y) & ABS2_MASK;
            accA[k] = ffma2(s0, av.x, accA[k]);
            accB[k] = ffma2(s1, av.y, accB[k]);
        }
    }

    float ss = 0.f;
    const float cj = cJs[tx];
    #pragma unroll
    for (int k = 0; k < 4; k++) {
        const ull t = fadd2(accA[k], accB[k]);
        const float absSum = lo_f(t) + hi_f(t);
        const float e = fmaf(0.4f, absSum, cIs[ty + 8 * k] + cj);
        const int i = it + ty + 8 * k;
        const int adjv = adj[(b * N + i) * N + jt + tx];
        g_e[(b * N + i) * N + jt + tx] = adjv ? e : -INFINITY;
        ss = fmaf(e, e, ss);
    }

    #pragma unroll
    for (int off = 16; off > 0; off >>= 1)
        ss += __shfl_xor_sync(0xFFFFFFFFu, ss, off);

    __shared__ float wsum[8];
    if (tx == 0) wsum[ty] = ss;
    __syncthreads();
    if (tid == 0) {
        float t = 0.f;
        #pragma unroll
        for (int w = 0; w < 8; w++) t += wsum[w];
        g_part[(blockIdx.z * (N/TI) + blockIdx.y) * (N/TJ) + blockIdx.x] = t;
    }
}

// ---------------------------------------------------------------------------
// Kernel F (fused): norm-reduce + softmax(8 rows) + att@Wh + ELU
// grid: (N/MT, B) = 128 CTAs, block: 256
//   thread: o8 = tx&15 (8 o's), idx16 = tx>>4, row = idx16&7, kh = idx16>>3
//   (each warp has uniform kh; K split in halves, reduced via smem at the end)
// ---------------------------------------------------------------------------
__global__ void k_fused(float* __restrict__ out) {
    const int b  = blockIdx.y;
    const int i0 = blockIdx.x * MT;
    const int tx = threadIdx.x;

    __shared__ float att_s[MT][N];        // 16 KB (also reused as reduce buffer)
    __shared__ float wh_s[2][KTF][FO];    // 16 KB
    __shared__ float rnorm[MT];
    __shared__ float s_inv;

    // ---- phase 0: deterministic norm reduction (same order in every CTA) ----
    {
        float* red = &att_s[0][0];
        red[tx] = g_part[tx] + g_part[tx + 256];
        __syncthreads();
        #pragma unroll
        for (int s = 128; s > 0; s >>= 1) {
            if (tx < s) red[tx] += red[tx + s];
            __syncthreads();
        }
        if (tx == 0) s_inv = 1.0f / sqrtf(red[0]);
        __syncthreads();
    }
    const float inv = s_inv;

    // ---- phase 1: softmax weights (unnormalized exp) for 8 rows ----
    {
        const int w = tx >> 5, lane = tx & 31;
        const float4* e4 = reinterpret_cast<const float4*>(g_e + (b * N + i0 + w) * N);
        float4* att4 = reinterpret_cast<float4*>(&att_s[w][0]);

        float4 ev[4];
        float mx = -INFINITY;
        #pragma unroll
        for (int m = 0; m < 4; m++) {
            const int c = lane + 32 * m;
            float4 v = e4[c];
            v.x *= inv; v.y *= inv; v.z *= inv; v.w *= inv;   // -inf stays -inf
            ev[m] = v;
            mx = fmaxf(mx, fmaxf(fmaxf(v.x, v.y), fmaxf(v.z, v.w)));
        }
        #pragma unroll
        for (int off = 16; off > 0; off >>= 1)
            mx = fmaxf(mx, __shfl_xor_sync(0xFFFFFFFFu, mx, off));

        float sum = 0.f;
        #pragma unroll
        for (int m = 0; m < 4; m++) {
            float4 v = ev[m];
            v.x = __expf(v.x - mx);
            v.y = __expf(v.y - mx);
            v.z = __expf(v.z - mx);
            v.w = __expf(v.w - mx);
            att4[lane + 32 * m] = v;
            sum += (v.x + v.y) + (v.z + v.w);
        }
        #pragma unroll
        for (int off = 16; off > 0; off >>= 1)
            sum += __shfl_xor_sync(0xFFFFFFFFu, sum, off);
        if (lane == 0) rnorm[w] = 1.0f / sum;
    }
    __syncthreads();

    // ---- phase 2: GEMM  h'[row, o] = sum_j att[row][j] * Wh[b, j, o] ----
    const int o8    = tx & 15;            // 8 consecutive o's
    const int idx16 = tx >> 4;
    const int row   = idx16 & 7;
    const int kh    = idx16 >> 3;         // K half: uniform per warp

    ull acc01 = 0, acc23 = 0, acc45 = 0, acc67 = 0;

    for (int kt = 0; kt < N / 2; kt += KTF) {
        // load Wh tiles for both K halves: 2*KTF*FO floats = 1024 float4
        #pragma unroll
        for (int p = 0; p < 4; p++) {
            const int idx = tx + 256 * p;
            const int h  = idx >> 9;
            const int kk = (idx >> 5) & 15;
            const int o4 = idx & 31;
            reinterpret_cast<float4*>(&wh_s[h][kk][0])[o4] =
                reinterpret_cast<const float4*>(g_Wh + (b * N + h * (N/2) + kt + kk) * FO)[o4];
        }
        __syncthreads();

        #pragma unroll
        for (int kk = 0; kk < KTF; kk++) {
            const float a = att_s[row][kh * (N/2) + kt + kk];
            ull a2; asm("mov.b64 %0, {%1, %1};" : "=l"(a2) : "r"(__float_as_uint(a)));
            const ulonglong2* wp =
                reinterpret_cast<const ulonglong2*>(&wh_s[kh][kk][o8 * 8]);
            const ulonglong2 wA = wp[0];
            const ulonglong2 wB = wp[1];
            acc01 = ffma2(a2, wA.x, acc01);
            acc23 = ffma2(a2, wA.y, acc23);
            acc45 = ffma2(a2, wB.x, acc45);
            acc67 = ffma2(a2, wB.y, acc67);
        }
        __syncthreads();
    }

    // ---- phase 3: combine K halves (fixed order), normalize, ELU, store ----
    float4* stage = reinterpret_cast<float4*>(&wh_s[0][0][0]);  // 4 KB staging
    if (kh == 1) {
        stage[(row * 16 + o8) * 2 + 0] =
            make_float4(lo_f(acc01), hi_f(acc01), lo_f(acc23), hi_f(acc23));
        stage[(row * 16 + o8) * 2 + 1] =
            make_float4(lo_f(acc45), hi_f(acc45), lo_f(acc67), hi_f(acc67));
    }
    __syncthreads();
    if (kh == 0) {
        const float4 p0 = stage[(row * 16 + o8) * 2 + 0];
        const float4 p1 = stage[(row * 16 + o8) * 2 + 1];
        const float rn = rnorm[row];
        float r[8];
        r[0] = (lo_f(acc01) + p0.x) * rn;
        r[1] = (hi_f(acc01) + p0.y) * rn;
        r[2] = (lo_f(acc23) + p0.z) * rn;
        r[3] = (hi_f(acc23) + p0.w) * rn;
        r[4] = (lo_f(acc45) + p1.x) * rn;
        r[5] = (hi_f(acc45) + p1.y) * rn;
        r[6] = (lo_f(acc67) + p1.z) * rn;
        r[7] = (hi_f(acc67) + p1.w) * rn;
        #pragma unroll
        for (int q = 0; q < 8; q++)
            r[q] = (r[q] > 0.f) ? r[q] : expm1f(r[q]);
        float4* dst = reinterpret_cast<float4*>(out + (b * N + i0 + row) * FO + o8 * 8);
        dst[0] = make_float4(r[0], r[1], r[2], r[3]);
        dst[1] = make_float4(r[4], r[5], r[6], r[7]);
    }
}

// ---------------------------------------------------------------------------
extern "C" void kernel_launch(void* const* d_in, const int* in_sizes, int n_in,
                              void* d_out, int out_size) {
    const float* x    = (const float*)d_in[0];   // [B,N,FI]
    const int*   adj  = (const int*)  d_in[1];   // [B,N,N]
    const float* W    = (const float*)d_in[2];   // [FI,FO]
    const float* a_fc = (const float*)d_in[3];   // [FO]
    float* out = (float*)d_out;                  // [B,N,FO]

    k_gemm <<< B * N / 4, 128 >>>(x, W, a_fc);
    k_edges<<< dim3(N/TJ, N/TI, B), dim3(32, 8) >>>(a_fc, adj);
    k_fused<<< dim3(N/MT, B), 256 >>>(out);
}

// round 6
// speedup vs baseline: 1.2482x; 1.2482x over previous
#include <cuda_runtime.h>
#include <cuda_bf16.h>
#include <math.h>

// Problem constants
#define B  2
#define N  512
#define FI 256
#define FO 128
#define ALPHA 0.2f

#define TI 32
#define TJ 32
#define NTILE (B * (N/TI) * (N/TJ))   // 512 e-tiles
#define NCTA  128
#define NTHR  256

typedef unsigned long long ull;

// Scratch (no allocations allowed -> device globals)
__device__ float g_Wh[B * N * FO];     // 512 KB
__device__ float g_e [B * N * N];      // 2 MB (masked e: -inf where adj==0)
__device__ float g_c [B * N];          // ci = sum_o a_o * Wh[i,o]
__device__ float g_part[NTILE];

// grid-barrier state (zero-init; reset by last CTA each launch -> replay-safe)
__device__ unsigned g_bar_cnt[2];
__device__ unsigned g_bar_flag[2];
__device__ unsigned g_done;

__device__ __forceinline__ ull fadd2(ull a, ull b) {
    ull d; asm("add.rn.f32x2 %0, %1, %2;" : "=l"(d) : "l"(a), "l"(b)); return d;
}
__device__ __forceinline__ ull ffma2(ull a, ull b, ull c) {
    ull d; asm("fma.rn.f32x2 %0, %1, %2, %3;" : "=l"(d) : "l"(a), "l"(b), "l"(c)); return d;
}
__device__ __forceinline__ float lo_f(ull v) { return __uint_as_float((unsigned)(v & 0xFFFFFFFFull)); }
__device__ __forceinline__ float hi_f(ull v) { return __uint_as_float((unsigned)(v >> 32)); }

#define ABS2_MASK 0x7FFFFFFF7FFFFFFFull

__device__ __forceinline__ void grid_barrier(int slot) {
    __syncthreads();
    if (threadIdx.x == 0) {
        __threadfence();
        unsigned t = atomicAdd(&g_bar_cnt[slot], 1);
        if (t == NCTA - 1) {
            atomicExch(&g_bar_flag[slot], 1u);
        } else {
            while (*((volatile unsigned*)&g_bar_flag[slot]) == 0u) {}
        }
        __threadfence();
    }
    __syncthreads();
}

// ---- overlapping shared-memory layouts ----
struct SmemP1 {
    float  xs[8][FI];        // 8 KB
    float4 wt[32][FO/4];     // 16 KB
};
struct SmemP2 {
    float4 tIs[TI * 33];     // 16.9 KB
    float4 tJs[TJ * 33];     // 16.9 KB
    float4 aS[FO / 4];
    float  cIs[TI];
    float  cJs[TJ];
    float  wsum[8];
};
struct SmemP34 {
    float  att[8][N];        // 16 KB
    float4 wht[32][FO/4];    // 16 KB
    float  red[NTHR];        // 1 KB
    float  rnorm[8];
};

__global__ void __launch_bounds__(NTHR, 1)
k_all(const float* __restrict__ x, const int* __restrict__ adj,
      const float* __restrict__ W, const float* __restrict__ a_fc,
      float* __restrict__ out) {
    __shared__ __align__(16) char smem_raw[36000];
    const int cta = blockIdx.x;
    const int tx  = threadIdx.x;

    // ======================= P1: Wh = x @ W  (+ ci) =======================
    {
        SmemP1& s = *reinterpret_cast<SmemP1*>(smem_raw);
        const int row0 = cta * 8;
        {
            const float4* x4 = reinterpret_cast<const float4*>(x + row0 * FI);
            float4* xs4 = reinterpret_cast<float4*>(&s.xs[0][0]);
            xs4[tx]        = x4[tx];
            xs4[tx + NTHR] = x4[tx + NTHR];
        }
        const int r    = tx >> 5;      // row within CTA (warp per row)
        const int lane = tx & 31;      // float4 column
        const float4* W4 = reinterpret_cast<const float4*>(W);
        float4 acc = make_float4(0.f, 0.f, 0.f, 0.f);

        for (int kt = 0; kt < FI; kt += 32) {
            __syncthreads();
            #pragma unroll
            for (int p = 0; p < 4; p++) {
                const int idx = tx + NTHR * p;       // 0..1023
                const int k  = idx >> 5;
                const int o4 = idx & 31;
                s.wt[k][o4] = W4[(kt + k) * (FO/4) + o4];
            }
            __syncthreads();
            #pragma unroll
            for (int k = 0; k < 32; k++) {
                const float  xv = s.xs[r][kt + k];   // warp broadcast
                const float4 w  = s.wt[k][lane];     // conflict-free LDS.128
                acc.x = fmaf(xv, w.x, acc.x);
                acc.y = fmaf(xv, w.y, acc.y);
                acc.z = fmaf(xv, w.z, acc.z);
                acc.w = fmaf(xv, w.w, acc.w);
            }
        }
        reinterpret_cast<float4*>(g_Wh)[(row0 + r) * (FO/4) + lane] = acc;

        const float4 av = reinterpret_cast<const float4*>(a_fc)[lane];
        float m = acc.x * av.x + acc.y * av.y + acc.z * av.z + acc.w * av.w;
        #pragma unroll
        for (int off = 16; off > 0; off >>= 1)
            m += __shfl_xor_sync(0xFFFFFFFFu, m, off);
        if (lane == 0) g_c[row0 + r] = m;
    }
    grid_barrier(0);

    // ======================= P2: masked e + norm partials =======================
    {
        SmemP2& s = *reinterpret_cast<SmemP2*>(smem_raw);
        const int lx = tx & 31;
        const int ty = tx >> 5;
        const float4* Wh4 = reinterpret_cast<const float4*>(g_Wh);

        if (tx < FO / 4)
            s.aS[tx] = reinterpret_cast<const float4*>(a_fc)[tx];

        for (int t = 0; t < 4; t++) {
            const int tile = cta * 4 + t;
            const int b  = tile >> 8;
            const int it = ((tile >> 4) & 15) * TI;
            const int jt = (tile & 15) * TJ;

            __syncthreads();   // smem reuse from previous tile / phase
            if (tx >= 64 && tx < 96)   s.cIs[tx - 64] = 0.6f * g_c[b * N + it + (tx - 64)];
            if (tx >= 96 && tx < 128)  s.cJs[tx - 96] = 0.6f * g_c[b * N + jt + (tx - 96)];
            #pragma unroll
            for (int p = 0; p < 4; p++) {
                const int idx = tx + NTHR * p;
                const int r = idx >> 5, c = idx & 31;
                s.tIs[r * 33 + c] = Wh4[(b * N + it + r) * (FO / 4) + c];
                s.tJs[r * 33 + c] = Wh4[(b * N + jt + r) * (FO / 4) + c];
            }
            __syncthreads();

            const ulonglong2* tI2 = reinterpret_cast<const ulonglong2*>(s.tIs);
            const ulonglong2* tJ2 = reinterpret_cast<const ulonglong2*>(s.tJs);
            const ulonglong2* a2  = reinterpret_cast<const ulonglong2*>(s.aS);

            ull accA[4] = {0, 0, 0, 0};
            ull accB[4] = {0, 0, 0, 0};

            #pragma unroll 4
            for (int oc = 0; oc < FO / 4; oc++) {
                const ulonglong2 wj = tJ2[lx * 33 + oc];   // lane-varying
                const ulonglong2 av = a2[oc];              // broadcast
                #pragma unroll
                for (int k = 0; k < 4; k++) {
                    const ulonglong2 wi = tI2[(ty + 8 * k) * 33 + oc];  // warp bcast
                    ull s0 = fadd2(wi.x, wj.x) & ABS2_MASK;
                    ull s1 = fadd2(wi.y, wj.y) & ABS2_MASK;
                    accA[k] = ffma2(s0, av.x, accA[k]);
                    accB[k] = ffma2(s1, av.y, accB[k]);
                }
            }

            float ss = 0.f;
            const float cj = s.cJs[lx];
            #pragma unroll
            for (int k = 0; k < 4; k++) {
                const ull tt = fadd2(accA[k], accB[k]);
                const float absSum = lo_f(tt) + hi_f(tt);
                const float e = fmaf(0.4f, absSum, s.cIs[ty + 8 * k] + cj);
                const int i = it + ty + 8 * k;
                const int adjv = adj[(b * N + i) * N + jt + lx];
                g_e[(b * N + i) * N + jt + lx] = adjv ? e : -INFINITY;
                ss = fmaf(e, e, ss);   // norm uses UNMASKED e (reference order)
            }

            #pragma unroll
            for (int off = 16; off > 0; off >>= 1)
                ss += __shfl_xor_sync(0xFFFFFFFFu, ss, off);
            if (lx == 0) s.wsum[ty] = ss;
            __syncthreads();
            if (tx == 0) {
                float acc = 0.f;
                #pragma unroll
                for (int w = 0; w < 8; w++) acc += s.wsum[w];
                g_part[tile] = acc;
            }
        }
    }
    grid_barrier(1);

    // ============== P2.5 norm + P3 softmax + P4 att@Wh + ELU ==============
    {
        SmemP34& s = *reinterpret_cast<SmemP34*>(smem_raw);
        const int b  = cta >> 6;
        const int i0 = (cta & 63) * 8;

        // --- P2.5: redundant deterministic norm reduction (identical order) ---
        s.red[tx] = g_part[tx] + g_part[tx + 256];
        __syncthreads();
        #pragma unroll
        for (int st = 128; st > 0; st >>= 1) {
            if (tx < st) s.red[tx] += s.red[tx + st];
            __syncthreads();
        }
        const float inv = 1.0f / sqrtf(s.red[0]);
        __syncthreads();

        // --- P3: softmax weights (unnormalized exp) for this CTA's 8 rows ---
        {
            const int w = tx >> 5, lane = tx & 31;
            const float4* e4 = reinterpret_cast<const float4*>(g_e + (b * N + i0 + w) * N);
            float4* att4 = reinterpret_cast<float4*>(&s.att[w][0]);

            float4 ev[4];
            float mx = -INFINITY;
            #pragma unroll
            for (int m = 0; m < 4; m++) {
                const int c = lane + 32 * m;
                float4 v = e4[c];
                v.x *= inv; v.y *= inv; v.z *= inv; v.w *= inv;  // -inf stays -inf
                ev[m] = v;
                mx = fmaxf(mx, fmaxf(fmaxf(v.x, v.y), fmaxf(v.z, v.w)));
            }
            #pragma unroll
            for (int off = 16; off > 0; off >>= 1)
                mx = fmaxf(mx, __shfl_xor_sync(0xFFFFFFFFu, mx, off));

            float sum = 0.f;
            #pragma unroll
            for (int m = 0; m < 4; m++) {
                float4 v = ev[m];
                v.x = __expf(v.x - mx);
                v.y = __expf(v.y - mx);
                v.z = __expf(v.z - mx);
                v.w = __expf(v.w - mx);
                att4[lane + 32 * m] = v;
                sum += (v.x + v.y) + (v.z + v.w);
            }
            #pragma unroll
            for (int off = 16; off > 0; off >>= 1)
                sum += __shfl_xor_sync(0xFFFFFFFFu, sum, off);
            if (lane == 0) s.rnorm[w] = 1.0f / sum;
        }
        __syncthreads();

        // --- P4: h'[row, o] = sum_j att[row][j] * Wh[b, j, o] ---
        const int iy = tx >> 5;        // warp = row
        const int o4 = tx & 31;        // float4 column
        float4 acc = make_float4(0.f, 0.f, 0.f, 0.f);

        for (int kt = 0; kt < N; kt += 32) {
            __syncthreads();
            #pragma unroll
            for (int p = 0; p < 4; p++) {
                const int idx = tx + NTHR * p;
                const int kk = idx >> 5, oc = idx & 31;
                s.wht[kk][oc] = reinterpret_cast<const float4*>(
                    g_Wh + (b * N + kt + kk) * FO)[oc];
            }
            __syncthreads();
            #pragma unroll
            for (int k = 0; k < 32; k++) {
                const float  a = s.att[iy][kt + k];  // warp broadcast
                const float4 w = s.wht[k][o4];       // conflict-free LDS.128
                acc.x = fmaf(a, w.x, acc.x);
                acc.y = fmaf(a, w.y, acc.y);
                acc.z = fmaf(a, w.z, acc.z);
                acc.w = fmaf(a, w.w, acc.w);
            }
        }

        const float rn = s.rnorm[iy];
        float4 v;
        v.x = acc.x * rn; v.y = acc.y * rn; v.z = acc.z * rn; v.w = acc.w * rn;
        v.x = (v.x > 0.f) ? v.x : expm1f(v.x);
        v.y = (v.y > 0.f) ? v.y : expm1f(v.y);
        v.z = (v.z > 0.f) ? v.z : expm1f(v.z);
        v.w = (v.w > 0.f) ? v.w : expm1f(v.w);
        reinterpret_cast<float4*>(out + (b * N + i0 + iy) * FO)[o4] = v;
    }

    // ---- reset barrier state for the next graph replay ----
    __syncthreads();
    if (tx == 0) {
        __threadfence();
        if (atomicAdd(&g_done, 1) == NCTA - 1) {
            g_bar_cnt[0] = 0; g_bar_cnt[1] = 0;
            g_bar_flag[0] = 0; g_bar_flag[1] = 0;
            g_done = 0;
            __threadfence();
        }
    }
}

// ---------------------------------------------------------------------------
extern "C" void kernel_launch(void* const* d_in, const int* in_sizes, int n_in,
                              void* d_out, int out_size) {
    const float* x    = (const float*)d_in[0];   // [B,N,FI]
    const int*   adj  = (const int*)  d_in[1];   // [B,N,N]
    const float* W    = (const float*)d_in[2];   // [FI,FO]
    const float* a_fc = (const float*)d_in[3];   // [FO]
    float* out = (float*)d_out;                  // [B,N,FO]

    k_all<<< NCTA, NTHR >>>(x, adj, W, a_fc, out);
}